// round 7
// baseline (speedup 1.0000x reference)
#include <cuda_runtime.h>
#include <cuda_bf16.h>
#include <cstdint>

// CameraSpline pose evaluation.
// Inputs (metadata order): t [M] f32, ctrl_trans [K,3] f32, ctrl_quats [K,4] f32, N [1] i32.
// Output: R [M,3,3] flattened (9*M floats) followed by T [M,3] (3*M floats).
//
// R6 -> R7: warp-cooperative gather. L1 cost of diverged loads = lines touched
// per instruction (32/instr when every lane has its own line). We precompute a
// 128B per-interval record (tangents + normalized quats baked in) and fetch it
// cooperatively: one LDG.128 covers 4 whole records (4 lines) -> 32 line-
// wavefronts/warp instead of 256. Records stage in pad-33 smem rows
// (conflict-free), outputs reuse the same rows, coalesced float4 writeback.

#define TPB 128
#define WARPS (TPB / 32)
#define ROWF 33                    // 32 payload floats + 1 pad
#define WS_FLOATS (32 * ROWF)      // per-warp staging
#define CAPI 524288                // max intervals in the record table

// One 128B record per interval i:
//  [0:3)  p0   [3:6)  m0   [6:9)  p1   [9:12) m1
//  [12:16) q_i  [16:20) q_i1  [20:24) q_im1  [24:28) q_ip2  [28:32) pad
__device__ __align__(128) float g_rec[(size_t)CAPI * 32];

__device__ __forceinline__ float4 qnormalize(float4 q) {
    float inv = rsqrtf(q.x * q.x + q.y * q.y + q.z * q.z + q.w * q.w);
    return make_float4(q.x * inv, q.y * inv, q.z * inv, q.w * inv);
}

__device__ __forceinline__ float4 qslerp(float4 q0, float4 q1, float u) {
    float dot = q0.x * q1.x + q0.y * q1.y + q0.z * q1.z + q0.w * q1.w;
    dot = fminf(fmaxf(dot, -1.0f), 1.0f);
    float sgn = (dot < 0.0f) ? -1.0f : 1.0f;
    float ad = fminf(fabsf(dot), 1.0f);
    float theta = acosf(ad);
    float st = __sinf(theta);
    float w0, w1;
    if (fabsf(st) > 1e-6f) {
        float inv = __frcp_rn(st);
        w0 = __sinf((1.0f - u) * theta) * inv;
        w1 = __sinf(u * theta) * inv;
    } else {
        w0 = 1.0f - u;
        w1 = u;
    }
    w1 *= sgn;
    return make_float4(w0 * q0.x + w1 * q1.x,
                       w0 * q0.y + w1 * q1.y,
                       w0 * q0.z + w1 * q1.z,
                       w0 * q0.w + w1 * q1.w);
}

// ---------------------------------------------------------------------------
// Precompute: one 128B record per interval, written coalesced via smem.
// ---------------------------------------------------------------------------
__global__ __launch_bounds__(TPB)
void precompute_intervals(const float* __restrict__ trans,
                          const float* __restrict__ quats,
                          int K)
{
    __shared__ float s[WARPS * WS_FLOATS];
    int lane = threadIdx.x & 31;
    int wid = threadIdx.x >> 5;
    float* ws = s + wid * WS_FLOATS;
    int nIv = K - 1;
    int base = (blockIdx.x * WARPS + wid) * 32;
    if (base >= nIv) return;

    int i = min(base + lane, nIv - 1);     // clamp; extra rows never stored
    {
        int im1 = max(i - 1, 0);
        int ip2 = min(i + 2, K - 1);
        float p0x = trans[3*i+0], p0y = trans[3*i+1], p0z = trans[3*i+2];
        float p1x = trans[3*(i+1)+0], p1y = trans[3*(i+1)+1], p1z = trans[3*(i+1)+2];
        float pmx = trans[3*im1+0], pmy = trans[3*im1+1], pmz = trans[3*im1+2];
        float ppx = trans[3*ip2+0], ppy = trans[3*ip2+1], ppz = trans[3*ip2+2];

        float d01x = p1x - p0x, d01y = p1y - p0y, d01z = p1z - p0z;
        float m0x, m0y, m0z, m1x, m1y, m1z;
        if (i > 0) { m0x = 0.5f*(p1x - pmx); m0y = 0.5f*(p1y - pmy); m0z = 0.5f*(p1z - pmz); }
        else       { m0x = d01x; m0y = d01y; m0z = d01z; }
        if (i + 1 < K - 1) { m1x = 0.5f*(ppx - p0x); m1y = 0.5f*(ppy - p0y); m1z = 0.5f*(ppz - p0z); }
        else               { m1x = d01x; m1y = d01y; m1z = d01z; }

        const float4* q4 = (const float4*)quats;
        float4 qi  = qnormalize(q4[i]);
        float4 qi1 = qnormalize(q4[i + 1]);
        float4 qm  = qnormalize(q4[im1]);
        float4 qp  = qnormalize(q4[ip2]);

        float* row = ws + lane * ROWF;
        row[0]=p0x; row[1]=p0y; row[2]=p0z;
        row[3]=m0x; row[4]=m0y; row[5]=m0z;
        row[6]=p1x; row[7]=p1y; row[8]=p1z;
        row[9]=m1x; row[10]=m1y; row[11]=m1z;
        row[12]=qi.x;  row[13]=qi.y;  row[14]=qi.z;  row[15]=qi.w;
        row[16]=qi1.x; row[17]=qi1.y; row[18]=qi1.z; row[19]=qi1.w;
        row[20]=qm.x;  row[21]=qm.y;  row[22]=qm.z;  row[23]=qm.w;
        row[24]=qp.x;  row[25]=qp.y;  row[26]=qp.z;  row[27]=qp.w;
        row[28]=0.0f; row[29]=0.0f; row[30]=0.0f; row[31]=0.0f;
    }
    __syncwarp();

    // Cooperative coalesced write-out: step covers 4 records, 8 lanes each.
    int r = lane & 7;
    int dq = lane >> 3;
    #pragma unroll
    for (int step = 0; step < 8; ++step) {
        int q = step * 4 + dq;
        int gi = base + q;
        if (gi < nIv) {
            const float* src = ws + q * ROWF + r * 4;
            float4 v = make_float4(src[0], src[1], src[2], src[3]);
            ((float4*)(g_rec + (size_t)gi * 32))[r] = v;
        }
    }
}

// ---------------------------------------------------------------------------
// Main kernel: warp-cooperative record fetch + compute + coalesced writeback.
// ---------------------------------------------------------------------------
__global__ __launch_bounds__(TPB)
void camera_spline_kernel(const float* __restrict__ t,
                          const int* __restrict__ Nptr,
                          float* __restrict__ out,
                          int M, int K)
{
    __shared__ float s[WARPS * WS_FLOATS];
    int lane = threadIdx.x & 31;
    int wid = threadIdx.x >> 5;
    float* ws = s + wid * WS_FLOATS;
    int warpBase = blockIdx.x * TPB + wid * 32;
    int m = warpBase + lane;

    int N = __ldg(Nptr);
    float km1 = (float)(K - 1);
    float nm1 = (float)max(N - 1, 1);
    // Match XLA rounding EXACTLY: t_ctrl = fl( fl(t*(K-1)) * fl(1/(N-1)) )
    float rcp = __fdiv_rn(1.0f, nm1);
    float tv = (m < M) ? t[m] : 0.0f;
    float tc = __fmul_rn(__fmul_rn(tv, km1), rcp);
    float fi = floorf(tc);
    int i = min(max((int)fi, 0), K - 2);
    float u = tc - (float)i;

    // ---- cooperative fetch: 8 LDG.128, each covering 4 whole records ----
    int r = lane & 7;
    int dq = lane >> 3;
    float4 v[8];
    #pragma unroll
    for (int step = 0; step < 8; ++step) {
        int q = step * 4 + dq;
        int idx = __shfl_sync(0xffffffffu, i, q);
        v[step] = ((const float4*)(g_rec + (size_t)idx * 32))[r];
    }
    #pragma unroll
    for (int step = 0; step < 8; ++step) {
        int q = step * 4 + dq;
        float* dst = ws + q * ROWF + r * 4;
        dst[0] = v[step].x; dst[1] = v[step].y; dst[2] = v[step].z; dst[3] = v[step].w;
    }
    __syncwarp();

    // ---- compute (reads own row: conflict-free, bank = lane + c mod 32) ----
    {
        const float* rec = ws + lane * ROWF;
        float p0x = rec[0], p0y = rec[1], p0z = rec[2];
        float m0x = rec[3], m0y = rec[4], m0z = rec[5];
        float p1x = rec[6], p1y = rec[7], p1z = rec[8];
        float m1x = rec[9], m1y = rec[10], m1z = rec[11];
        float4 q_i  = make_float4(rec[12], rec[13], rec[14], rec[15]);
        float4 q_i1 = make_float4(rec[16], rec[17], rec[18], rec[19]);
        float4 q_m  = make_float4(rec[20], rec[21], rec[22], rec[23]);
        float4 q_p  = make_float4(rec[24], rec[25], rec[26], rec[27]);

        float u2 = u * u;
        float u3 = u2 * u;
        float h00 = 2.0f * u3 - 3.0f * u2 + 1.0f;
        float h10 = u3 - 2.0f * u2 + u;
        float h01 = -2.0f * u3 + 3.0f * u2;
        float h11 = u3 - u2;

        float Tx = h00 * p0x + h10 * m0x + h01 * p1x + h11 * m1x;
        float Ty = h00 * p0y + h10 * m0y + h01 * p1y + h11 * m1y;
        float Tz = h00 * p0z + h10 * m0z + h01 * p1z + h11 * m1z;

        float4 s_main = qslerp(q_i, q_i1, u);
        float4 s_aux  = qslerp(q_m, q_p, u);
        float u_sq = 2.0f * u * (1.0f - u);
        float4 q = qnormalize(qslerp(s_main, s_aux, u_sq));

        float w = q.x, x = q.y, y = q.z, z = q.w;
        float xx = x * x, yy = y * y, zz = z * z;
        float xy = x * y, xz = x * z, yz = y * z;
        float wx = w * x, wy = w * y, wz = w * z;

        // overwrite own row with the 12 outputs (row-private, no sync needed)
        float* orow = ws + lane * ROWF;
        orow[0] = 1.0f - 2.0f * (yy + zz);
        orow[1] = 2.0f * (xy - wz);
        orow[2] = 2.0f * (xz + wy);
        orow[3] = 2.0f * (xy + wz);
        orow[4] = 1.0f - 2.0f * (xx + zz);
        orow[5] = 2.0f * (yz - wx);
        orow[6] = 2.0f * (xz - wy);
        orow[7] = 2.0f * (yz + wx);
        orow[8] = 1.0f - 2.0f * (xx + yy);
        orow[9]  = Tx;
        orow[10] = Ty;
        orow[11] = Tz;
    }
    __syncwarp();

    // ---- warp-local coalesced writeback ----
    int count = min(32, M - warpBase);
    if (count <= 0) return;

    if (count == 32) {
        // R: 32*9 = 288 floats = 72 float4 (warpBase*9 is 4-aligned: warpBase%32==0)
        float4* outR4 = (float4*)(out + (size_t)warpBase * 9);
        #pragma unroll
        for (int n = lane; n < 72; n += 32) {
            int e = n << 2;
            float4 vv;
            vv.x = ws[(e + 0) / 9 * ROWF + (e + 0) % 9];
            vv.y = ws[(e + 1) / 9 * ROWF + (e + 1) % 9];
            vv.z = ws[(e + 2) / 9 * ROWF + (e + 2) % 9];
            vv.w = ws[(e + 3) / 9 * ROWF + (e + 3) % 9];
            outR4[n] = vv;
        }
        // T: 32*3 = 96 floats = 24 float4, base = M*9 + warpBase*3
        size_t tBase = (size_t)M * 9 + (size_t)warpBase * 3;
        if ((tBase & 3) == 0) {
            float4* outT4 = (float4*)(out + tBase);
            if (lane < 24) {
                int e = lane << 2;
                float4 vv;
                vv.x = ws[(e + 0) / 3 * ROWF + 9 + (e + 0) % 3];
                vv.y = ws[(e + 1) / 3 * ROWF + 9 + (e + 1) % 3];
                vv.z = ws[(e + 2) / 3 * ROWF + 9 + (e + 2) % 3];
                vv.w = ws[(e + 3) / 3 * ROWF + 9 + (e + 3) % 3];
                outT4[lane] = vv;
            }
        } else {
            float* outT = out + tBase;
            for (int e = lane; e < 96; e += 32)
                outT[e] = ws[e / 3 * ROWF + 9 + e % 3];
        }
    } else {
        // tail warp: scalar
        float* outR = out + (size_t)warpBase * 9;
        for (int e = lane; e < count * 9; e += 32)
            outR[e] = ws[e / 9 * ROWF + e % 9];
        float* outT = out + (size_t)M * 9 + (size_t)warpBase * 3;
        for (int e = lane; e < count * 3; e += 32)
            outT[e] = ws[e / 3 * ROWF + 9 + e % 3];
    }
}

// ---------------------------------------------------------------------------
// Fallback for K-1 > CAPI: direct gather (R5-style).
// ---------------------------------------------------------------------------
__global__ __launch_bounds__(256)
void camera_spline_kernel_direct(const float* __restrict__ t,
                                 const float* __restrict__ ctrl_trans,
                                 const float* __restrict__ ctrl_quats,
                                 const int* __restrict__ Nptr,
                                 float* __restrict__ out,
                                 int M, int K)
{
    int m = blockIdx.x * blockDim.x + threadIdx.x;
    if (m >= M) return;

    int N = __ldg(Nptr);
    float km1 = (float)(K - 1);
    float nm1 = (float)max(N - 1, 1);
    float rcp = __fdiv_rn(1.0f, nm1);
    float tc = __fmul_rn(__fmul_rn(t[m], km1), rcp);
    float fi = floorf(tc);
    int i = min(max((int)fi, 0), K - 2);
    float u = tc - (float)i;
    int im1 = max(i - 1, 0);
    int ip2 = min(i + 2, K - 1);

    float3 p0 = make_float3(ctrl_trans[3*i+0], ctrl_trans[3*i+1], ctrl_trans[3*i+2]);
    float3 p1 = make_float3(ctrl_trans[3*(i+1)+0], ctrl_trans[3*(i+1)+1], ctrl_trans[3*(i+1)+2]);
    float3 pm = make_float3(ctrl_trans[3*im1+0], ctrl_trans[3*im1+1], ctrl_trans[3*im1+2]);
    float3 pp = make_float3(ctrl_trans[3*ip2+0], ctrl_trans[3*ip2+1], ctrl_trans[3*ip2+2]);

    float3 d01 = make_float3(p1.x - p0.x, p1.y - p0.y, p1.z - p0.z);
    float3 m0 = (i > 0) ? make_float3(0.5f*(p1.x-pm.x), 0.5f*(p1.y-pm.y), 0.5f*(p1.z-pm.z)) : d01;
    float3 m1 = (i + 1 < K - 1) ? make_float3(0.5f*(pp.x-p0.x), 0.5f*(pp.y-p0.y), 0.5f*(pp.z-p0.z)) : d01;

    float u2 = u * u, u3 = u2 * u;
    float h00 = 2.0f*u3 - 3.0f*u2 + 1.0f;
    float h10 = u3 - 2.0f*u2 + u;
    float h01 = -2.0f*u3 + 3.0f*u2;
    float h11 = u3 - u2;
    float Tx = h00*p0.x + h10*m0.x + h01*p1.x + h11*m1.x;
    float Ty = h00*p0.y + h10*m0.y + h01*p1.y + h11*m1.y;
    float Tz = h00*p0.z + h10*m0.z + h01*p1.z + h11*m1.z;

    const float4* quats = (const float4*)ctrl_quats;
    float4 q_i  = qnormalize(quats[i]);
    float4 q_i1 = qnormalize(quats[i + 1]);
    float4 q_m  = qnormalize(quats[im1]);
    float4 q_p  = qnormalize(quats[ip2]);
    float4 s_main = qslerp(q_i, q_i1, u);
    float4 s_aux  = qslerp(q_m, q_p, u);
    float4 q = qnormalize(qslerp(s_main, s_aux, 2.0f * u * (1.0f - u)));

    float w = q.x, x = q.y, y = q.z, z = q.w;
    float* R = out + (size_t)m * 9;
    R[0] = 1.0f - 2.0f * (y*y + z*z);
    R[1] = 2.0f * (x*y - w*z);
    R[2] = 2.0f * (x*z + w*y);
    R[3] = 2.0f * (x*y + w*z);
    R[4] = 1.0f - 2.0f * (x*x + z*z);
    R[5] = 2.0f * (y*z - w*x);
    R[6] = 2.0f * (x*z - w*y);
    R[7] = 2.0f * (y*z + w*x);
    R[8] = 1.0f - 2.0f * (x*x + y*y);
    float* Tout = out + (size_t)M * 9 + (size_t)m * 3;
    Tout[0] = Tx; Tout[1] = Ty; Tout[2] = Tz;
}

extern "C" void kernel_launch(void* const* d_in, const int* in_sizes, int n_in,
                              void* d_out, int out_size)
{
    const float* t          = (const float*)d_in[0];
    const float* ctrl_trans = (const float*)d_in[1];
    const float* ctrl_quats = (const float*)d_in[2];
    const int*   Nptr       = (const int*)d_in[3];

    int M = in_sizes[0];
    int K = in_sizes[1] / 3;

    float* out = (float*)d_out;

    if (K - 1 <= CAPI) {
        int nIv = K - 1;
        int pblocks = (nIv + TPB - 1) / TPB;
        precompute_intervals<<<pblocks, TPB>>>(ctrl_trans, ctrl_quats, K);
        int blocks = (M + TPB - 1) / TPB;
        camera_spline_kernel<<<blocks, TPB>>>(t, Nptr, out, M, K);
    } else {
        int blocks = (M + 255) / 256;
        camera_spline_kernel_direct<<<blocks, 256>>>(t, ctrl_trans, ctrl_quats, Nptr, out, M, K);
    }
}

// round 9
// speedup vs baseline: 1.3446x; 1.3446x over previous
#include <cuda_runtime.h>
#include <cuda_bf16.h>
#include <cstdint>

// CameraSpline pose evaluation.
// Inputs (metadata order): t [M] f32, ctrl_trans [K,3] f32, ctrl_quats [K,4] f32, N [1] i32.
// Output: R [M,3,3] flattened (9*M floats) followed by T [M,3] (3*M floats).
//
// R7 -> R8 (resubmitted R9; R8 bench was an infra failure):
//  * 128B per-interval record now carries precomputed slerp constants
//    (theta, 1/sin(theta), sign-folded quats) for the two outer slerps ->
//    per-thread trig drops from ~3 acos + 9 sin to 1 acos + 5 sin.
//  * XOR-swizzled float4 smem staging (conflict-free STS.128/LDS.128).
//  * Outputs scatter-stored (q*9+c, 9 coprime 32 -> conflict-free), written
//    back as linear LDS.128 + __stcs STG.128 (evict-first keeps the record
//    table L2-resident; removes all /9 %9 ALU).

#define TPB 128
#define WARPS (TPB / 32)
#define CAPI 524288                // max intervals in the record table

// One 128B record (8 float4 parts) per interval i:
//  p0: p0x p0y p0z m0x | p1: m0y m0z p1x p1y | p2: p1z m1x m1y m1z
//  p3: q_i | p4: q_i1_adj (sign folded) | p5: thm ism tha isa
//  p6: q_im1 | p7: q_ip2_adj (sign folded)
__device__ __align__(128) float4 g_rec[(size_t)CAPI * 8];

__device__ __forceinline__ float4 qnormalize(float4 q) {
    float inv = rsqrtf(q.x * q.x + q.y * q.y + q.z * q.z + q.w * q.w);
    return make_float4(q.x * inv, q.y * inv, q.z * inv, q.w * inv);
}

// Full slerp (used for the squad blend and the direct fallback).
__device__ __forceinline__ float4 qslerp(float4 q0, float4 q1, float u) {
    float dot = q0.x * q1.x + q0.y * q1.y + q0.z * q1.z + q0.w * q1.w;
    dot = fminf(fmaxf(dot, -1.0f), 1.0f);
    float sgn = (dot < 0.0f) ? -1.0f : 1.0f;
    float ad = fminf(fabsf(dot), 1.0f);
    float theta = acosf(ad);
    float st = __sinf(theta);
    float w0, w1;
    if (fabsf(st) > 1e-6f) {
        float inv = __frcp_rn(st);
        w0 = __sinf((1.0f - u) * theta) * inv;
        w1 = __sinf(u * theta) * inv;
    } else {
        w0 = 1.0f - u;
        w1 = u;
    }
    w1 *= sgn;
    return make_float4(w0 * q0.x + w1 * q1.x,
                       w0 * q0.y + w1 * q1.y,
                       w0 * q0.z + w1 * q1.z,
                       w0 * q0.w + w1 * q1.w);
}

// ---------------------------------------------------------------------------
// Precompute: one 128B record per interval, written coalesced via smem.
// ---------------------------------------------------------------------------
#define ROWF 33
__global__ __launch_bounds__(TPB)
void precompute_intervals(const float* __restrict__ trans,
                          const float* __restrict__ quats,
                          int K)
{
    __shared__ float s[WARPS * 32 * ROWF];
    int lane = threadIdx.x & 31;
    int wid = threadIdx.x >> 5;
    float* ws = s + wid * 32 * ROWF;
    int nIv = K - 1;
    int base = (blockIdx.x * WARPS + wid) * 32;
    if (base >= nIv) return;

    int i = min(base + lane, nIv - 1);     // clamp; extra rows never stored
    {
        int im1 = max(i - 1, 0);
        int ip2 = min(i + 2, K - 1);
        float p0x = trans[3*i+0], p0y = trans[3*i+1], p0z = trans[3*i+2];
        float p1x = trans[3*(i+1)+0], p1y = trans[3*(i+1)+1], p1z = trans[3*(i+1)+2];
        float pmx = trans[3*im1+0], pmy = trans[3*im1+1], pmz = trans[3*im1+2];
        float ppx = trans[3*ip2+0], ppy = trans[3*ip2+1], ppz = trans[3*ip2+2];

        float d01x = p1x - p0x, d01y = p1y - p0y, d01z = p1z - p0z;
        float m0x, m0y, m0z, m1x, m1y, m1z;
        if (i > 0) { m0x = 0.5f*(p1x - pmx); m0y = 0.5f*(p1y - pmy); m0z = 0.5f*(p1z - pmz); }
        else       { m0x = d01x; m0y = d01y; m0z = d01z; }
        if (i + 1 < K - 1) { m1x = 0.5f*(ppx - p0x); m1y = 0.5f*(ppy - p0y); m1z = 0.5f*(ppz - p0z); }
        else               { m1x = d01x; m1y = d01y; m1z = d01z; }

        const float4* q4 = (const float4*)quats;
        float4 qi  = qnormalize(q4[i]);
        float4 qi1 = qnormalize(q4[i + 1]);
        float4 qm  = qnormalize(q4[im1]);
        float4 qp  = qnormalize(q4[ip2]);

        // main slerp constants
        float dm = qi.x*qi1.x + qi.y*qi1.y + qi.z*qi1.z + qi.w*qi1.w;
        dm = fminf(fmaxf(dm, -1.0f), 1.0f);
        float sgnm = (dm < 0.0f) ? -1.0f : 1.0f;
        float thm = acosf(fminf(fabsf(dm), 1.0f));
        float stm = __sinf(thm);
        float ism = (fabsf(stm) > 1e-6f) ? __frcp_rn(stm) : 0.0f;
        float4 qi1a = make_float4(sgnm*qi1.x, sgnm*qi1.y, sgnm*qi1.z, sgnm*qi1.w);

        // aux slerp constants
        float da = qm.x*qp.x + qm.y*qp.y + qm.z*qp.z + qm.w*qp.w;
        da = fminf(fmaxf(da, -1.0f), 1.0f);
        float sgna = (da < 0.0f) ? -1.0f : 1.0f;
        float tha = acosf(fminf(fabsf(da), 1.0f));
        float sta = __sinf(tha);
        float isa = (fabsf(sta) > 1e-6f) ? __frcp_rn(sta) : 0.0f;
        float4 qpa = make_float4(sgna*qp.x, sgna*qp.y, sgna*qp.z, sgna*qp.w);

        float* row = ws + lane * ROWF;
        row[0]=p0x;  row[1]=p0y;  row[2]=p0z;  row[3]=m0x;
        row[4]=m0y;  row[5]=m0z;  row[6]=p1x;  row[7]=p1y;
        row[8]=p1z;  row[9]=m1x;  row[10]=m1y; row[11]=m1z;
        row[12]=qi.x;  row[13]=qi.y;  row[14]=qi.z;  row[15]=qi.w;
        row[16]=qi1a.x; row[17]=qi1a.y; row[18]=qi1a.z; row[19]=qi1a.w;
        row[20]=thm;  row[21]=ism;  row[22]=tha;  row[23]=isa;
        row[24]=qm.x;  row[25]=qm.y;  row[26]=qm.z;  row[27]=qm.w;
        row[28]=qpa.x; row[29]=qpa.y; row[30]=qpa.z; row[31]=qpa.w;
    }
    __syncwarp();

    // Cooperative coalesced write-out: each step covers 4 records, 8 lanes each.
    int r = lane & 7;
    int dq = lane >> 3;
    #pragma unroll
    for (int step = 0; step < 8; ++step) {
        int q = step * 4 + dq;
        int gi = base + q;
        if (gi < nIv) {
            const float* src = ws + q * ROWF + r * 4;
            g_rec[(size_t)gi * 8 + r] = make_float4(src[0], src[1], src[2], src[3]);
        }
    }
}

// ---------------------------------------------------------------------------
// Main kernel: warp-cooperative record fetch + compute + coalesced writeback.
// ---------------------------------------------------------------------------
__global__ __launch_bounds__(TPB)
void camera_spline_kernel(const float* __restrict__ t,
                          const int* __restrict__ Nptr,
                          float* __restrict__ out,
                          int M, int K)
{
    __shared__ float4 s4[WARPS * 256];     // 256 float4 (1KB payload region) per warp
    int lane = threadIdx.x & 31;
    int wid = threadIdx.x >> 5;
    float4* ws4 = s4 + wid * 256;
    float* wsf = (float*)ws4;
    int warpBase = blockIdx.x * TPB + wid * 32;
    int m = warpBase + lane;

    int N = __ldg(Nptr);
    float km1 = (float)(K - 1);
    float nm1 = (float)max(N - 1, 1);
    // Match XLA rounding EXACTLY: t_ctrl = fl( fl(t*(K-1)) * fl(1/(N-1)) )
    float rcp = __fdiv_rn(1.0f, nm1);
    float tv = (m < M) ? t[m] : 0.0f;
    float tc = __fmul_rn(__fmul_rn(tv, km1), rcp);
    float fi = floorf(tc);
    int i = min(max((int)fi, 0), K - 2);
    float u = tc - (float)i;

    // ---- cooperative fetch: 8 LDG.128, each covering 4 whole records ----
    int r = lane & 7;
    int dq = lane >> 3;
    float4 v[8];
    #pragma unroll
    for (int step = 0; step < 8; ++step) {
        int q = step * 4 + dq;
        int idx = __shfl_sync(0xffffffffu, i, q);
        v[step] = g_rec[(size_t)idx * 8 + r];
    }
    #pragma unroll
    for (int step = 0; step < 8; ++step) {
        int q = step * 4 + dq;
        ws4[q * 8 + (r ^ (q & 7))] = v[step];      // XOR swizzle: conflict-free
    }
    __syncwarp();

    // ---- read own record: 8 conflict-free LDS.128 ----
    int q7 = lane & 7;
    float4 P0 = ws4[lane * 8 + (0 ^ q7)];
    float4 P1 = ws4[lane * 8 + (1 ^ q7)];
    float4 P2 = ws4[lane * 8 + (2 ^ q7)];
    float4 P3 = ws4[lane * 8 + (3 ^ q7)];
    float4 P4 = ws4[lane * 8 + (4 ^ q7)];
    float4 P5 = ws4[lane * 8 + (5 ^ q7)];
    float4 P6 = ws4[lane * 8 + (6 ^ q7)];
    float4 P7 = ws4[lane * 8 + (7 ^ q7)];

    // ---- compute ----
    float u2 = u * u;
    float u3 = u2 * u;
    float h00 = 2.0f * u3 - 3.0f * u2 + 1.0f;
    float h10 = u3 - 2.0f * u2 + u;
    float h01 = -2.0f * u3 + 3.0f * u2;
    float h11 = u3 - u2;

    // translation (P0..P2): p0 p1 m0 m1
    float Tx = h00 * P0.x + h10 * P0.w + h01 * P1.z + h11 * P2.y;
    float Ty = h00 * P0.y + h10 * P1.x + h01 * P1.w + h11 * P2.z;
    float Tz = h00 * P0.z + h10 * P1.y + h01 * P2.x + h11 * P2.w;

    // outer slerps with precomputed theta / 1/sin(theta) / sign-folded quats
    float thm = P5.x, ism = P5.y, tha = P5.z, isa = P5.w;
    float w0m, w1m;
    if (ism != 0.0f) {
        w0m = __sinf((1.0f - u) * thm) * ism;
        w1m = __sinf(u * thm) * ism;
    } else {
        w0m = 1.0f - u;
        w1m = u;
    }
    float4 s_main = make_float4(w0m * P3.x + w1m * P4.x,
                                w0m * P3.y + w1m * P4.y,
                                w0m * P3.z + w1m * P4.z,
                                w0m * P3.w + w1m * P4.w);
    float w0a, w1a;
    if (isa != 0.0f) {
        w0a = __sinf((1.0f - u) * tha) * isa;
        w1a = __sinf(u * tha) * isa;
    } else {
        w0a = 1.0f - u;
        w1a = u;
    }
    float4 s_aux = make_float4(w0a * P6.x + w1a * P7.x,
                               w0a * P6.y + w1a * P7.y,
                               w0a * P6.z + w1a * P7.z,
                               w0a * P6.w + w1a * P7.w);

    float u_sq = 2.0f * u * (1.0f - u);
    float4 q = qnormalize(qslerp(s_main, s_aux, u_sq));

    float w = q.x, x = q.y, y = q.z, z = q.w;
    float xx = x * x, yy = y * y, zz = z * z;
    float xy = x * y, xz = x * z, yz = y * z;
    float wx = w * x, wy = w * y, wz = w * z;

    __syncwarp();   // all record reads done before staging overwrites them

    // ---- scatter outputs: R at q*9+c (9 coprime 32 -> conflict-free),
    //      T at 288 + q*3 + c ----
    if (m < M) {
        float* rr = wsf + lane * 9;
        rr[0] = 1.0f - 2.0f * (yy + zz);
        rr[1] = 2.0f * (xy - wz);
        rr[2] = 2.0f * (xz + wy);
        rr[3] = 2.0f * (xy + wz);
        rr[4] = 1.0f - 2.0f * (xx + zz);
        rr[5] = 2.0f * (yz - wx);
        rr[6] = 2.0f * (xz - wy);
        rr[7] = 2.0f * (yz + wx);
        rr[8] = 1.0f - 2.0f * (xx + yy);
        float* tt = wsf + 288 + lane * 3;
        tt[0] = Tx; tt[1] = Ty; tt[2] = Tz;
    }
    __syncwarp();

    // ---- warp-local coalesced writeback (evict-first stores) ----
    int count = min(32, M - warpBase);
    if (count <= 0) return;

    if (count == 32) {
        float4* dstR = (float4*)(out + (size_t)warpBase * 9);   // warpBase%32==0 -> 16B aligned
        const float4* srcR = (const float4*)wsf;
        #pragma unroll
        for (int n = lane; n < 72; n += 32)
            __stcs(dstR + n, srcR[n]);
        size_t tBase = (size_t)M * 9 + (size_t)warpBase * 3;
        if ((tBase & 3) == 0) {
            float4* dstT = (float4*)(out + tBase);
            const float4* srcT = (const float4*)(wsf + 288);
            if (lane < 24)
                __stcs(dstT + lane, srcT[lane]);
        } else {
            float* dstT = out + tBase;
            for (int e = lane; e < 96; e += 32)
                dstT[e] = wsf[288 + e];
        }
    } else {
        float* dstR = out + (size_t)warpBase * 9;
        for (int e = lane; e < count * 9; e += 32)
            dstR[e] = wsf[e];
        float* dstT = out + (size_t)M * 9 + (size_t)warpBase * 3;
        for (int e = lane; e < count * 3; e += 32)
            dstT[e] = wsf[288 + e];
    }
}

// ---------------------------------------------------------------------------
// Fallback for K-1 > CAPI: direct gather.
// ---------------------------------------------------------------------------
__global__ __launch_bounds__(256)
void camera_spline_kernel_direct(const float* __restrict__ t,
                                 const float* __restrict__ ctrl_trans,
                                 const float* __restrict__ ctrl_quats,
                                 const int* __restrict__ Nptr,
                                 float* __restrict__ out,
                                 int M, int K)
{
    int m = blockIdx.x * blockDim.x + threadIdx.x;
    if (m >= M) return;

    int N = __ldg(Nptr);
    float km1 = (float)(K - 1);
    float nm1 = (float)max(N - 1, 1);
    float rcp = __fdiv_rn(1.0f, nm1);
    float tc = __fmul_rn(__fmul_rn(t[m], km1), rcp);
    float fi = floorf(tc);
    int i = min(max((int)fi, 0), K - 2);
    float u = tc - (float)i;
    int im1 = max(i - 1, 0);
    int ip2 = min(i + 2, K - 1);

    float3 p0 = make_float3(ctrl_trans[3*i+0], ctrl_trans[3*i+1], ctrl_trans[3*i+2]);
    float3 p1 = make_float3(ctrl_trans[3*(i+1)+0], ctrl_trans[3*(i+1)+1], ctrl_trans[3*(i+1)+2]);
    float3 pm = make_float3(ctrl_trans[3*im1+0], ctrl_trans[3*im1+1], ctrl_trans[3*im1+2]);
    float3 pp = make_float3(ctrl_trans[3*ip2+0], ctrl_trans[3*ip2+1], ctrl_trans[3*ip2+2]);

    float3 d01 = make_float3(p1.x - p0.x, p1.y - p0.y, p1.z - p0.z);
    float3 m0 = (i > 0) ? make_float3(0.5f*(p1.x-pm.x), 0.5f*(p1.y-pm.y), 0.5f*(p1.z-pm.z)) : d01;
    float3 m1 = (i + 1 < K - 1) ? make_float3(0.5f*(pp.x-p0.x), 0.5f*(pp.y-p0.y), 0.5f*(pp.z-p0.z)) : d01;

    float u2 = u * u, u3 = u2 * u;
    float h00 = 2.0f*u3 - 3.0f*u2 + 1.0f;
    float h10 = u3 - 2.0f*u2 + u;
    float h01 = -2.0f*u3 + 3.0f*u2;
    float h11 = u3 - u2;
    float Tx = h00*p0.x + h10*m0.x + h01*p1.x + h11*m1.x;
    float Ty = h00*p0.y + h10*m0.y + h01*p1.y + h11*m1.y;
    float Tz = h00*p0.z + h10*m0.z + h01*p1.z + h11*m1.z;

    const float4* quats = (const float4*)ctrl_quats;
    float4 q_i  = qnormalize(quats[i]);
    float4 q_i1 = qnormalize(quats[i + 1]);
    float4 q_m  = qnormalize(quats[im1]);
    float4 q_p  = qnormalize(quats[ip2]);
    float4 s_main = qslerp(q_i, q_i1, u);
    float4 s_aux  = qslerp(q_m, q_p, u);
    float4 q = qnormalize(qslerp(s_main, s_aux, 2.0f * u * (1.0f - u)));

    float w = q.x, x = q.y, y = q.z, z = q.w;
    float* R = out + (size_t)m * 9;
    R[0] = 1.0f - 2.0f * (y*y + z*z);
    R[1] = 2.0f * (x*y - w*z);
    R[2] = 2.0f * (x*z + w*y);
    R[3] = 2.0f * (x*y + w*z);
    R[4] = 1.0f - 2.0f * (x*x + z*z);
    R[5] = 2.0f * (y*z - w*x);
    R[6] = 2.0f * (x*z - w*y);
    R[7] = 2.0f * (y*z + w*x);
    R[8] = 1.0f - 2.0f * (x*x + y*y);
    float* Tout = out + (size_t)M * 9 + (size_t)m * 3;
    Tout[0] = Tx; Tout[1] = Ty; Tout[2] = Tz;
}

extern "C" void kernel_launch(void* const* d_in, const int* in_sizes, int n_in,
                              void* d_out, int out_size)
{
    const float* t          = (const float*)d_in[0];
    const float* ctrl_trans = (const float*)d_in[1];
    const float* ctrl_quats = (const float*)d_in[2];
    const int*   Nptr       = (const int*)d_in[3];

    int M = in_sizes[0];
    int K = in_sizes[1] / 3;

    float* out = (float*)d_out;

    if (K - 1 <= CAPI) {
        int nIv = K - 1;
        int pblocks = (nIv + TPB - 1) / TPB;
        precompute_intervals<<<pblocks, TPB>>>(ctrl_trans, ctrl_quats, K);
        int blocks = (M + TPB - 1) / TPB;
        camera_spline_kernel<<<blocks, TPB>>>(t, Nptr, out, M, K);
    } else {
        int blocks = (M + 255) / 256;
        camera_spline_kernel_direct<<<blocks, 256>>>(t, ctrl_trans, ctrl_quats, Nptr, out, M, K);
    }
}